// round 1
// baseline (speedup 1.0000x reference)
#include <cuda_runtime.h>
#include <math.h>

#define N_NODES 100000
#define N_EDGES 400000
#define E_TOT   500000
#define N_GRAPHS 2048
#define F_IN 78
#define H1N 10
#define C1  780      // 10*78
#define C1A 800      // +10 asrc +10 adst
#define OUT2 128
#define C2A 130      // +asrc +adst
#define NB_SCAN 98   // ceil(100000/1024)

// ---------------- scratch (device globals; no allocation allowed) -----------
__device__ float g_H1[N_NODES * C1A];       // 320 MB  x@W1aug
__device__ float g_H1O[N_NODES * C1];       // 312 MB  elu(gat1)
__device__ float g_H2[N_NODES * C2A];       // 52 MB   h1o@W2aug
__device__ float g_AS1[N_NODES * H1N], g_AD1[N_NODES * H1N];
__device__ float g_M1[N_NODES * H1N], g_RD1[N_NODES * H1N];
__device__ float g_AS2[N_NODES], g_AD2[N_NODES], g_M2[N_NODES], g_RD2[N_NODES];
__device__ int   g_DEG[N_NODES], g_INCL[N_NODES], g_BSUM[128], g_BOFF[128];
__device__ int   g_OFF[N_NODES + 1], g_CUR[N_NODES], g_CSRC[E_TOT];
__device__ float g_W1A[F_IN * C1A], g_W2A[C1 * C2A];
__device__ float g_HSUM[N_GRAPHS * OUT2], g_HMAX[N_GRAPHS * OUT2];
__device__ float g_XT[N_GRAPHS * 256], g_XC[N_GRAPHS * 512];
__device__ float g_X1[N_GRAPHS * 1024], g_X2[N_GRAPHS * 256];

// ---------------- CSR build -----------------------------------------------
__global__ void k_initdeg() {
    int i = blockIdx.x * blockDim.x + threadIdx.x;
    if (i < N_NODES) g_DEG[i] = 1;   // self loop
}
__global__ void k_hist(const int* __restrict__ ei) {
    int e = blockIdx.x * blockDim.x + threadIdx.x;
    if (e < N_EDGES) atomicAdd(&g_DEG[ei[N_EDGES + e]], 1);
}
__global__ void k_scan1() {
    __shared__ int sw[32];
    int i = blockIdx.x * 1024 + threadIdx.x;
    int v = (i < N_NODES) ? g_DEG[i] : 0;
    int lane = threadIdx.x & 31, w = threadIdx.x >> 5;
    int x = v;
#pragma unroll
    for (int o = 1; o < 32; o <<= 1) {
        int y = __shfl_up_sync(0xffffffffu, x, o);
        if (lane >= o) x += y;
    }
    if (lane == 31) sw[w] = x;
    __syncthreads();
    if (w == 0) {
        int s = sw[lane];
#pragma unroll
        for (int o = 1; o < 32; o <<= 1) {
            int y = __shfl_up_sync(0xffffffffu, s, o);
            if (lane >= o) s += y;
        }
        sw[lane] = s;
    }
    __syncthreads();
    if (w > 0) x += sw[w - 1];
    if (i < N_NODES) g_INCL[i] = x;
    if (threadIdx.x == 1023) g_BSUM[blockIdx.x] = x;
}
__global__ void k_scan2() {
    __shared__ int sw[4];
    int t = threadIdx.x;            // 128 threads
    int v = (t < NB_SCAN) ? g_BSUM[t] : 0;
    int lane = t & 31, w = t >> 5;
    int x = v;
#pragma unroll
    for (int o = 1; o < 32; o <<= 1) {
        int y = __shfl_up_sync(0xffffffffu, x, o);
        if (lane >= o) x += y;
    }
    if (lane == 31) sw[w] = x;
    __syncthreads();
    int add = 0;
    for (int i = 0; i < w; i++) add += sw[i];
    x += add;
    if (t < NB_SCAN) g_BOFF[t] = x - v;   // exclusive block offsets
}
__global__ void k_scan3() {
    int i = blockIdx.x * blockDim.x + threadIdx.x;
    if (i < N_NODES) {
        int off = g_INCL[i] - g_DEG[i] + g_BOFF[i >> 10];
        g_OFF[i] = off;
        g_CUR[i] = off;
        if (i == 0) g_OFF[N_NODES] = E_TOT;
    }
}
__global__ void k_scatter(const int* __restrict__ ei) {
    int i = blockIdx.x * blockDim.x + threadIdx.x;
    if (i >= E_TOT) return;
    int s, d;
    if (i < N_EDGES) { s = ei[i]; d = ei[N_EDGES + i]; }
    else             { s = d = i - N_EDGES; }
    int pos = atomicAdd(&g_CUR[d], 1);
    g_CSRC[pos] = s;
}

// ---------------- weight augmentation (fold attention vecs into W) ---------
__global__ void k_prep1(const float* __restrict__ W1, const float* __restrict__ as,
                        const float* __restrict__ ad) {
    int i = blockIdx.x * blockDim.x + threadIdx.x;
    if (i >= F_IN * C1A) return;
    int k = i / C1A, c = i - k * C1A;
    if (c < C1) { g_W1A[i] = W1[k * C1 + c]; return; }
    float s = 0.f;
    if (c < C1 + H1N) {
        int h = c - C1;
        for (int d = 0; d < F_IN; d++) s += W1[k * C1 + h * F_IN + d] * as[h * F_IN + d];
    } else {
        int h = c - C1 - H1N;
        for (int d = 0; d < F_IN; d++) s += W1[k * C1 + h * F_IN + d] * ad[h * F_IN + d];
    }
    g_W1A[i] = s;
}
__global__ void k_prep2(const float* __restrict__ W2, const float* __restrict__ as,
                        const float* __restrict__ ad) {
    int i = blockIdx.x * blockDim.x + threadIdx.x;
    if (i >= C1 * C2A) return;
    int k = i / C2A, c = i - k * C2A;
    if (c < OUT2) { g_W2A[i] = W2[k * OUT2 + c]; return; }
    const float* a = (c == OUT2) ? as : ad;
    float s = 0.f;
    for (int d = 0; d < OUT2; d++) s += W2[k * OUT2 + d] * a[d];
    g_W2A[i] = s;
}

// ---------------- generic GEMM: blockDim.x == N, ROWS rows per block --------
template <int ROWS, int VEC>
__global__ void k_gemm(const float* __restrict__ A, const float* __restrict__ B,
                       const float* __restrict__ bias, float* __restrict__ C,
                       int M, int K, int N, int act) {
    extern __shared__ __align__(16) float sA[];
    int r0 = blockIdx.x * ROWS;
    for (int i = threadIdx.x; i < ROWS * K; i += blockDim.x) {
        int r = i / K;
        sA[i] = (r0 + r < M) ? A[(r0 + r) * K + (i - r * K)] : 0.f;
    }
    __syncthreads();
    int c = threadIdx.x;
    if (c >= N) return;
    float acc[ROWS];
#pragma unroll
    for (int r = 0; r < ROWS; r++) acc[r] = 0.f;
    for (int k = 0; k < K; k += VEC) {
        float b0 = B[k * N + c];
        float b1 = (VEC > 1) ? B[(k + 1) * N + c] : 0.f;
        float b2 = (VEC > 3) ? B[(k + 2) * N + c] : 0.f;
        float b3 = (VEC > 3) ? B[(k + 3) * N + c] : 0.f;
#pragma unroll
        for (int r = 0; r < ROWS; r++) {
            if (VEC == 4) {
                float4 a = *reinterpret_cast<const float4*>(&sA[r * K + k]);
                acc[r] = fmaf(a.x, b0, acc[r]);
                acc[r] = fmaf(a.y, b1, acc[r]);
                acc[r] = fmaf(a.z, b2, acc[r]);
                acc[r] = fmaf(a.w, b3, acc[r]);
            } else if (VEC == 2) {
                float2 a = *reinterpret_cast<const float2*>(&sA[r * K + k]);
                acc[r] = fmaf(a.x, b0, acc[r]);
                acc[r] = fmaf(a.y, b1, acc[r]);
            } else {
                acc[r] = fmaf(sA[r * K + k], b0, acc[r]);
            }
        }
    }
    float bv = bias ? bias[c] : 0.f;
#pragma unroll
    for (int r = 0; r < ROWS; r++) {
        if (r0 + r < M) {
            float v = acc[r] + bv;
            if (act) v = fmaxf(v, 0.f);
            C[(r0 + r) * N + c] = v;
        }
    }
}

// ---------------- layer 1 softmax / aggregation -----------------------------
__global__ void k_compact1() {
    int i = blockIdx.x * blockDim.x + threadIdx.x;
    if (i >= N_NODES * H1N) return;
    int n = i / H1N, h = i - n * H1N;
    g_AS1[i] = g_H1[n * C1A + C1 + h];
    g_AD1[i] = g_H1[n * C1A + C1 + H1N + h];
}
__global__ void k_softmax1() {
    int i = blockIdx.x * blockDim.x + threadIdx.x;
    if (i >= N_NODES * H1N) return;
    int n = i / H1N, h = i - n * H1N;
    float adst = g_AD1[i];
    int p0 = g_OFF[n], p1 = g_OFF[n + 1];
    float m = -1e30f;
    for (int p = p0; p < p1; p++) {
        float e = g_AS1[g_CSRC[p] * H1N + h] + adst;
        e = e > 0.f ? e : 0.2f * e;
        m = fmaxf(m, e);
    }
    float den = 0.f;
    for (int p = p0; p < p1; p++) {
        float e = g_AS1[g_CSRC[p] * H1N + h] + adst;
        e = e > 0.f ? e : 0.2f * e;
        den += expf(e - m);
    }
    g_M1[i] = m;
    g_RD1[i] = 1.f / (den + 1e-16f);
}
__global__ void k_agg1(const float* __restrict__ b1) {
    int n = blockIdx.x, tid = threadIdx.x;
    __shared__ int ssrc[16];
    __shared__ float sal[160];
    __shared__ float sadst[H1N], sm[H1N], srd[H1N];
    if (tid < H1N) {
        sadst[tid] = g_AD1[n * H1N + tid];
        sm[tid] = g_M1[n * H1N + tid];
        srd[tid] = g_RD1[n * H1N + tid];
    }
    int c0 = tid, c1 = tid + 256, c2 = tid + 512, c3 = tid + 768;
    int h0 = c0 / F_IN, h1 = c1 / F_IN, h2 = c2 / F_IN;
    int h3 = (c3 < C1) ? c3 / F_IN : 0;
    float a0 = 0.f, a1 = 0.f, a2 = 0.f, a3 = 0.f;
    int p0 = g_OFF[n], p1 = g_OFF[n + 1];
    for (int p = p0; p < p1; p += 16) {
        int cnt = min(16, p1 - p);
        __syncthreads();
        if (tid < cnt) ssrc[tid] = g_CSRC[p + tid];
        __syncthreads();
        if (tid < cnt * H1N) {
            int e = tid / H1N, h = tid - e * H1N;
            float ev = g_AS1[ssrc[e] * H1N + h] + sadst[h];
            ev = ev > 0.f ? ev : 0.2f * ev;
            sal[tid] = expf(ev - sm[h]) * srd[h];
        }
        __syncthreads();
        for (int e = 0; e < cnt; e++) {
            const float* hr = &g_H1[ssrc[e] * C1A];
            a0 = fmaf(sal[e * H1N + h0], hr[c0], a0);
            a1 = fmaf(sal[e * H1N + h1], hr[c1], a1);
            a2 = fmaf(sal[e * H1N + h2], hr[c2], a2);
            if (c3 < C1) a3 = fmaf(sal[e * H1N + h3], hr[c3], a3);
        }
    }
    float v;
    v = a0 + b1[c0]; g_H1O[n * C1 + c0] = v > 0.f ? v : expm1f(v);
    v = a1 + b1[c1]; g_H1O[n * C1 + c1] = v > 0.f ? v : expm1f(v);
    v = a2 + b1[c2]; g_H1O[n * C1 + c2] = v > 0.f ? v : expm1f(v);
    if (c3 < C1) { v = a3 + b1[c3]; g_H1O[n * C1 + c3] = v > 0.f ? v : expm1f(v); }
}

// ---------------- layer 2 softmax / aggregation + readout -------------------
__global__ void k_compact2() {
    int n = blockIdx.x * blockDim.x + threadIdx.x;
    if (n >= N_NODES) return;
    g_AS2[n] = g_H2[n * C2A + OUT2];
    g_AD2[n] = g_H2[n * C2A + OUT2 + 1];
}
__global__ void k_softmax2() {
    int n = blockIdx.x * blockDim.x + threadIdx.x;
    if (n >= N_NODES) return;
    float adst = g_AD2[n];
    int p0 = g_OFF[n], p1 = g_OFF[n + 1];
    float m = -1e30f;
    for (int p = p0; p < p1; p++) {
        float e = g_AS2[g_CSRC[p]] + adst;
        e = e > 0.f ? e : 0.2f * e;
        m = fmaxf(m, e);
    }
    float den = 0.f;
    for (int p = p0; p < p1; p++) {
        float e = g_AS2[g_CSRC[p]] + adst;
        e = e > 0.f ? e : 0.2f * e;
        den += expf(e - m);
    }
    g_M2[n] = m;
    g_RD2[n] = 1.f / (den + 1e-16f);
}
__global__ void k_zero_readout() {
    int i = blockIdx.x * blockDim.x + threadIdx.x;
    if (i < N_GRAPHS * OUT2) { g_HSUM[i] = 0.f; g_HMAX[i] = 0.f; }
}
__global__ void k_agg2(const float* __restrict__ b2, const float* __restrict__ wg,
                       const float* __restrict__ bg, const int* __restrict__ batch) {
    int n = blockIdx.x, tid = threadIdx.x;
    __shared__ int ssrc[16];
    __shared__ float sal[16];
    __shared__ float red[128];
    float adst = g_AD2[n], m = g_M2[n], rd = g_RD2[n];
    float acc = 0.f;
    int p0 = g_OFF[n], p1 = g_OFF[n + 1];
    for (int p = p0; p < p1; p += 16) {
        int cnt = min(16, p1 - p);
        __syncthreads();
        if (tid < cnt) {
            int s = g_CSRC[p + tid];
            ssrc[tid] = s;
            float ev = g_AS2[s] + adst;
            ev = ev > 0.f ? ev : 0.2f * ev;
            sal[tid] = expf(ev - m) * rd;
        }
        __syncthreads();
        for (int e = 0; e < cnt; e++)
            acc = fmaf(sal[e], g_H2[ssrc[e] * C2A + tid], acc);
    }
    float v = fmaxf(acc + b2[tid], 0.f);
    red[tid] = v * wg[tid];
    __syncthreads();
    for (int o = 64; o > 0; o >>= 1) {
        if (tid < o) red[tid] += red[tid + o];
        __syncthreads();
    }
    float w = 1.f / (1.f + expf(-(red[0] + bg[0])));
    int g = batch[n];
    atomicAdd(&g_HSUM[g * OUT2 + tid], v * w);
    atomicMax((int*)&g_HMAX[g * OUT2 + tid], __float_as_int(v));  // v >= 0
}

// ---------------- tail ------------------------------------------------------
__global__ void k_concat() {
    int i = blockIdx.x * blockDim.x + threadIdx.x;
    if (i >= N_GRAPHS * 512) return;
    int g = i / 512, c = i - g * 512;
    float v;
    if (c < 128)      v = g_HSUM[g * 128 + c];
    else if (c < 256) v = g_HMAX[g * 128 + (c - 128)];
    else              v = g_XT[g * 256 + (c - 256)];
    g_XC[i] = v;
}
__global__ void k_out(const float* __restrict__ Wo, const float* __restrict__ bo,
                      float* __restrict__ out) {
    int g = blockIdx.x, lane = threadIdx.x;
    float s = 0.f;
    for (int k = lane; k < 256; k += 32) s += g_X2[g * 256 + k] * Wo[k];
#pragma unroll
    for (int o = 16; o > 0; o >>= 1) s += __shfl_down_sync(0xffffffffu, s, o);
    if (lane == 0) out[g] = s + bo[0];
}

// ---------------- host ------------------------------------------------------
extern "C" void kernel_launch(void* const* d_in, const int* in_sizes, int n_in,
                              void* d_out, int out_size) {
    const float* x      = (const float*)d_in[0];
    const int*   ei     = (const int*)d_in[1];
    const int*   batch  = (const int*)d_in[2];
    const float* target = (const float*)d_in[3];
    const float* W1  = (const float*)d_in[4];
    const float* as1 = (const float*)d_in[5];
    const float* ad1 = (const float*)d_in[6];
    const float* b1  = (const float*)d_in[7];
    const float* W2  = (const float*)d_in[8];
    const float* as2 = (const float*)d_in[9];
    const float* ad2 = (const float*)d_in[10];
    const float* b2  = (const float*)d_in[11];
    const float* wg  = (const float*)d_in[12];
    const float* bg  = (const float*)d_in[13];
    const float* Wxt = (const float*)d_in[14];
    const float* bxt = (const float*)d_in[15];
    const float* Wf1 = (const float*)d_in[16];
    const float* bf1 = (const float*)d_in[17];
    const float* Wf2 = (const float*)d_in[18];
    const float* bf2 = (const float*)d_in[19];
    const float* Wo  = (const float*)d_in[20];
    const float* bo  = (const float*)d_in[21];
    float* out = (float*)d_out;

    float *H1, *H1O, *H2, *W1A, *W2A, *XT, *XC, *X1, *X2;
    cudaGetSymbolAddress((void**)&H1,  g_H1);
    cudaGetSymbolAddress((void**)&H1O, g_H1O);
    cudaGetSymbolAddress((void**)&H2,  g_H2);
    cudaGetSymbolAddress((void**)&W1A, g_W1A);
    cudaGetSymbolAddress((void**)&W2A, g_W2A);
    cudaGetSymbolAddress((void**)&XT,  g_XT);
    cudaGetSymbolAddress((void**)&XC,  g_XC);
    cudaGetSymbolAddress((void**)&X1,  g_X1);
    cudaGetSymbolAddress((void**)&X2,  g_X2);

    // CSR build
    k_initdeg<<<(N_NODES + 255) / 256, 256>>>();
    k_hist<<<(N_EDGES + 255) / 256, 256>>>(ei);
    k_scan1<<<NB_SCAN, 1024>>>();
    k_scan2<<<1, 128>>>();
    k_scan3<<<(N_NODES + 255) / 256, 256>>>();
    k_scatter<<<(E_TOT + 255) / 256, 256>>>(ei);

    // weight augmentation
    k_prep1<<<(F_IN * C1A + 255) / 256, 256>>>(W1, as1, ad1);
    k_prep2<<<(C1 * C2A + 255) / 256, 256>>>(W2, as2, ad2);

    // layer 1
    k_gemm<8, 2><<<N_NODES / 8, C1A, 8 * F_IN * 4>>>(x, W1A, nullptr, H1,
                                                     N_NODES, F_IN, C1A, 0);
    k_compact1<<<(N_NODES * H1N + 255) / 256, 256>>>();
    k_softmax1<<<(N_NODES * H1N + 255) / 256, 256>>>();
    k_agg1<<<N_NODES, 256>>>(b1);

    // layer 2
    k_gemm<8, 4><<<N_NODES / 8, C2A, 8 * C1 * 4>>>(H1O, W2A, nullptr, H2,
                                                   N_NODES, C1, C2A, 0);
    k_compact2<<<(N_NODES + 255) / 256, 256>>>();
    k_softmax2<<<(N_NODES + 255) / 256, 256>>>();
    k_zero_readout<<<(N_GRAPHS * OUT2 + 255) / 256, 256>>>();
    k_agg2<<<N_NODES, 128>>>(b2, wg, bg, batch);

    // tail MLP
    k_gemm<8, 4><<<N_GRAPHS / 8, 256, 8 * 1280 * 4>>>(target, Wxt, bxt, XT,
                                                      N_GRAPHS, 1280, 256, 0);
    k_concat<<<(N_GRAPHS * 512 + 255) / 256, 256>>>();
    k_gemm<8, 4><<<N_GRAPHS / 8, 1024, 8 * 512 * 4>>>(XC, Wf1, bf1, X1,
                                                      N_GRAPHS, 512, 1024, 1);
    k_gemm<8, 4><<<N_GRAPHS / 8, 256, 8 * 1024 * 4>>>(X1, Wf2, bf2, X2,
                                                      N_GRAPHS, 1024, 256, 1);
    k_out<<<N_GRAPHS, 32>>>(Wo, bo, out);
}

// round 2
// speedup vs baseline: 1.7131x; 1.7131x over previous
#include <cuda_runtime.h>
#include <math.h>
#include <stdint.h>

#define N_NODES 100000
#define N_EDGES 400000
#define E_TOT   500000
#define N_GRAPHS 2048
#define F_IN 78
#define H1N 10
#define C1  780      // 10*78
#define C1A 800      // +10 asrc +10 adst
#define OUT2 128
#define C2A 130      // +asrc +adst
#define NB_SCAN 98   // ceil(100000/1024)

// ---------------- scratch (device globals; no allocation allowed) -----------
__device__ float g_H1[N_NODES * C1A];       // 320 MB  x@W1aug
__device__ float g_H1O[N_NODES * C1];       // 312 MB  elu(gat1)
__device__ float g_H2[N_NODES * C2A];       // 52 MB   h1o@W2aug
__device__ float g_AS1[N_NODES * H1N], g_AD1[N_NODES * H1N];
__device__ float g_M1[N_NODES * H1N], g_RD1[N_NODES * H1N];
__device__ float g_AS2[N_NODES], g_AD2[N_NODES], g_M2[N_NODES], g_RD2[N_NODES];
__device__ int   g_DEG[N_NODES], g_INCL[N_NODES], g_BSUM[128], g_BOFF[128];
__device__ int   g_OFF[N_NODES + 1], g_CUR[N_NODES], g_CSRC[E_TOT];
__device__ float g_W1A[F_IN * C1A], g_W2A[C1 * C2A];
__device__ float g_HSUM[N_GRAPHS * OUT2], g_HMAX[N_GRAPHS * OUT2];
__device__ float g_XT[N_GRAPHS * 256], g_XC[N_GRAPHS * 512];
__device__ float g_X1[N_GRAPHS * 1024], g_X2[N_GRAPHS * 256];

// ---------------- CSR build -----------------------------------------------
__global__ void k_initdeg() {
    int i = blockIdx.x * blockDim.x + threadIdx.x;
    if (i < N_NODES) g_DEG[i] = 1;   // self loop
}
__global__ void k_hist(const int* __restrict__ ei) {
    int e = blockIdx.x * blockDim.x + threadIdx.x;
    if (e < N_EDGES) atomicAdd(&g_DEG[ei[N_EDGES + e]], 1);
}
__global__ void k_scan1() {
    __shared__ int sw[32];
    int i = blockIdx.x * 1024 + threadIdx.x;
    int v = (i < N_NODES) ? g_DEG[i] : 0;
    int lane = threadIdx.x & 31, w = threadIdx.x >> 5;
    int x = v;
#pragma unroll
    for (int o = 1; o < 32; o <<= 1) {
        int y = __shfl_up_sync(0xffffffffu, x, o);
        if (lane >= o) x += y;
    }
    if (lane == 31) sw[w] = x;
    __syncthreads();
    if (w == 0) {
        int s = sw[lane];
#pragma unroll
        for (int o = 1; o < 32; o <<= 1) {
            int y = __shfl_up_sync(0xffffffffu, s, o);
            if (lane >= o) s += y;
        }
        sw[lane] = s;
    }
    __syncthreads();
    if (w > 0) x += sw[w - 1];
    if (i < N_NODES) g_INCL[i] = x;
    if (threadIdx.x == 1023) g_BSUM[blockIdx.x] = x;
}
__global__ void k_scan2() {
    __shared__ int sw[4];
    int t = threadIdx.x;            // 128 threads
    int v = (t < NB_SCAN) ? g_BSUM[t] : 0;
    int lane = t & 31, w = t >> 5;
    int x = v;
#pragma unroll
    for (int o = 1; o < 32; o <<= 1) {
        int y = __shfl_up_sync(0xffffffffu, x, o);
        if (lane >= o) x += y;
    }
    if (lane == 31) sw[w] = x;
    __syncthreads();
    int add = 0;
    for (int i = 0; i < w; i++) add += sw[i];
    x += add;
    if (t < NB_SCAN) g_BOFF[t] = x - v;   // exclusive block offsets
}
__global__ void k_scan3() {
    int i = blockIdx.x * blockDim.x + threadIdx.x;
    if (i < N_NODES) {
        int off = g_INCL[i] - g_DEG[i] + g_BOFF[i >> 10];
        g_OFF[i] = off;
        g_CUR[i] = off;
        if (i == 0) g_OFF[N_NODES] = E_TOT;
    }
}
__global__ void k_scatter(const int* __restrict__ ei) {
    int i = blockIdx.x * blockDim.x + threadIdx.x;
    if (i >= E_TOT) return;
    int s, d;
    if (i < N_EDGES) { s = ei[i]; d = ei[N_EDGES + i]; }
    else             { s = d = i - N_EDGES; }
    int pos = atomicAdd(&g_CUR[d], 1);
    g_CSRC[pos] = s;
}

// ---------------- weight augmentation (fold attention vecs into W) ---------
__global__ void k_prep1(const float* __restrict__ W1, const float* __restrict__ as,
                        const float* __restrict__ ad) {
    int i = blockIdx.x * blockDim.x + threadIdx.x;
    if (i >= F_IN * C1A) return;
    int k = i / C1A, c = i - k * C1A;
    if (c < C1) { g_W1A[i] = W1[k * C1 + c]; return; }
    float s = 0.f;
    if (c < C1 + H1N) {
        int h = c - C1;
        for (int d = 0; d < F_IN; d++) s += W1[k * C1 + h * F_IN + d] * as[h * F_IN + d];
    } else {
        int h = c - C1 - H1N;
        for (int d = 0; d < F_IN; d++) s += W1[k * C1 + h * F_IN + d] * ad[h * F_IN + d];
    }
    g_W1A[i] = s;
}
__global__ void k_prep2(const float* __restrict__ W2, const float* __restrict__ as,
                        const float* __restrict__ ad) {
    int i = blockIdx.x * blockDim.x + threadIdx.x;
    if (i >= C1 * C2A) return;
    int k = i / C2A, c = i - k * C2A;
    if (c < OUT2) { g_W2A[i] = W2[k * OUT2 + c]; return; }
    const float* a = (c == OUT2) ? as : ad;
    float s = 0.f;
    for (int d = 0; d < OUT2; d++) s += W2[k * OUT2 + d] * a[d];
    g_W2A[i] = s;
}

// ---------------- TF32 tensor-core GEMM: 64x64 block tile, 4 warps ----------
// A [M,K] row-major fp32, B [K,N] row-major fp32, C [M,N] row-major fp32.
// ldC = row stride of C (>= N). Guarded loads/stores so M,K,N can be ragged.
#define PA 20   // smem pitch for A (16 k cols padded) — conflict-free frag loads
#define PB 72   // smem pitch for B (64 n cols padded) — conflict-free frag loads

__device__ __forceinline__ uint32_t f2tf32(float v) {
    uint32_t u;
    asm("cvt.rna.tf32.f32 %0, %1;" : "=r"(u) : "f"(v));
    return u;
}

__global__ void k_mma(const float* __restrict__ A, const float* __restrict__ B,
                      const float* __restrict__ bias, float* __restrict__ C,
                      int M, int K, int N, int ldC, int act) {
    __shared__ float sA[64 * PA];
    __shared__ float sB[16 * PB];
    int t = threadIdx.x;
    int warp = t >> 5, lane = t & 31;
    int g = lane >> 2, tg = lane & 3;
    int wm = warp >> 1, wn = warp & 1;          // 2x2 warps
    int r0 = blockIdx.x * 64;
    int c0 = blockIdx.y * 64;

    float acc[2][4][4];
#pragma unroll
    for (int mi = 0; mi < 2; mi++)
#pragma unroll
        for (int ni = 0; ni < 4; ni++)
#pragma unroll
            for (int r = 0; r < 4; r++) acc[mi][ni][r] = 0.f;

    for (int kt = 0; kt < K; kt += 16) {
        // load A tile 64x16
#pragma unroll
        for (int i = 0; i < 8; i++) {
            int lin = t + i * 128;
            int row = lin >> 4, col = lin & 15;
            float v = 0.f;
            if (r0 + row < M && kt + col < K) v = A[(size_t)(r0 + row) * K + kt + col];
            sA[row * PA + col] = __uint_as_float(f2tf32(v));
        }
        // load B tile 16x64
#pragma unroll
        for (int i = 0; i < 8; i++) {
            int lin = t + i * 128;
            int row = lin >> 6, col = lin & 63;
            float v = 0.f;
            if (kt + row < K && c0 + col < N) v = B[(size_t)(kt + row) * N + c0 + col];
            sB[row * PB + col] = __uint_as_float(f2tf32(v));
        }
        __syncthreads();
#pragma unroll
        for (int kk = 0; kk < 16; kk += 8) {
            uint32_t af[2][4];
#pragma unroll
            for (int mi = 0; mi < 2; mi++) {
                int br = wm * 32 + mi * 16;
                af[mi][0] = __float_as_uint(sA[(br + g) * PA + kk + tg]);
                af[mi][1] = __float_as_uint(sA[(br + g + 8) * PA + kk + tg]);
                af[mi][2] = __float_as_uint(sA[(br + g) * PA + kk + tg + 4]);
                af[mi][3] = __float_as_uint(sA[(br + g + 8) * PA + kk + tg + 4]);
            }
            uint32_t bf[4][2];
#pragma unroll
            for (int ni = 0; ni < 4; ni++) {
                int bc = wn * 32 + ni * 8 + g;
                bf[ni][0] = __float_as_uint(sB[(kk + tg) * PB + bc]);
                bf[ni][1] = __float_as_uint(sB[(kk + tg + 4) * PB + bc]);
            }
#pragma unroll
            for (int mi = 0; mi < 2; mi++)
#pragma unroll
                for (int ni = 0; ni < 4; ni++) {
                    asm volatile(
                        "mma.sync.aligned.m16n8k8.row.col.f32.tf32.tf32.f32 "
                        "{%0,%1,%2,%3}, {%4,%5,%6,%7}, {%8,%9}, {%0,%1,%2,%3};\n"
                        : "+f"(acc[mi][ni][0]), "+f"(acc[mi][ni][1]),
                          "+f"(acc[mi][ni][2]), "+f"(acc[mi][ni][3])
                        : "r"(af[mi][0]), "r"(af[mi][1]), "r"(af[mi][2]), "r"(af[mi][3]),
                          "r"(bf[ni][0]), "r"(bf[ni][1]));
                }
        }
        __syncthreads();
    }
    // epilogue
#pragma unroll
    for (int mi = 0; mi < 2; mi++) {
#pragma unroll
        for (int ni = 0; ni < 4; ni++) {
            int col = c0 + wn * 32 + ni * 8 + tg * 2;
#pragma unroll
            for (int half = 0; half < 2; half++) {
                int row = r0 + wm * 32 + mi * 16 + g + half * 8;
                if (row < M) {
                    float v0 = acc[mi][ni][half * 2] ;
                    float v1 = acc[mi][ni][half * 2 + 1];
                    if (col < N) {
                        float v = v0 + (bias ? bias[col] : 0.f);
                        if (act) v = fmaxf(v, 0.f);
                        C[(size_t)row * ldC + col] = v;
                    }
                    if (col + 1 < N) {
                        float v = v1 + (bias ? bias[col + 1] : 0.f);
                        if (act) v = fmaxf(v, 0.f);
                        C[(size_t)row * ldC + col + 1] = v;
                    }
                }
            }
        }
    }
}

// ---------------- layer 1 softmax / aggregation -----------------------------
__global__ void k_compact1() {
    int i = blockIdx.x * blockDim.x + threadIdx.x;
    if (i >= N_NODES * H1N) return;
    int n = i / H1N, h = i - n * H1N;
    g_AS1[i] = g_H1[n * C1A + C1 + h];
    g_AD1[i] = g_H1[n * C1A + C1 + H1N + h];
}
__global__ void k_softmax1() {
    int i = blockIdx.x * blockDim.x + threadIdx.x;
    if (i >= N_NODES * H1N) return;
    int n = i / H1N, h = i - n * H1N;
    float adst = g_AD1[i];
    int p0 = g_OFF[n], p1 = g_OFF[n + 1];
    float m = -1e30f;
    for (int p = p0; p < p1; p++) {
        float e = g_AS1[g_CSRC[p] * H1N + h] + adst;
        e = e > 0.f ? e : 0.2f * e;
        m = fmaxf(m, e);
    }
    float den = 0.f;
    for (int p = p0; p < p1; p++) {
        float e = g_AS1[g_CSRC[p] * H1N + h] + adst;
        e = e > 0.f ? e : 0.2f * e;
        den += expf(e - m);
    }
    g_M1[i] = m;
    g_RD1[i] = 1.f / (den + 1e-16f);
}
__global__ void k_agg1(const float* __restrict__ b1) {
    int n = blockIdx.x, tid = threadIdx.x;
    __shared__ int ssrc[16];
    __shared__ float sal[160];
    __shared__ float sadst[H1N], sm[H1N], srd[H1N];
    if (tid < H1N) {
        sadst[tid] = g_AD1[n * H1N + tid];
        sm[tid] = g_M1[n * H1N + tid];
        srd[tid] = g_RD1[n * H1N + tid];
    }
    int c0 = tid, c1 = tid + 256, c2 = tid + 512, c3 = tid + 768;
    int h0 = c0 / F_IN, h1 = c1 / F_IN, h2 = c2 / F_IN;
    int h3 = (c3 < C1) ? c3 / F_IN : 0;
    float a0 = 0.f, a1 = 0.f, a2 = 0.f, a3 = 0.f;
    int p0 = g_OFF[n], p1 = g_OFF[n + 1];
    for (int p = p0; p < p1; p += 16) {
        int cnt = min(16, p1 - p);
        __syncthreads();
        if (tid < cnt) ssrc[tid] = g_CSRC[p + tid];
        __syncthreads();
        if (tid < cnt * H1N) {
            int e = tid / H1N, h = tid - e * H1N;
            float ev = g_AS1[ssrc[e] * H1N + h] + sadst[h];
            ev = ev > 0.f ? ev : 0.2f * ev;
            sal[tid] = expf(ev - sm[h]) * srd[h];
        }
        __syncthreads();
        for (int e = 0; e < cnt; e++) {
            const float* hr = &g_H1[(size_t)ssrc[e] * C1A];
            a0 = fmaf(sal[e * H1N + h0], hr[c0], a0);
            a1 = fmaf(sal[e * H1N + h1], hr[c1], a1);
            a2 = fmaf(sal[e * H1N + h2], hr[c2], a2);
            if (c3 < C1) a3 = fmaf(sal[e * H1N + h3], hr[c3], a3);
        }
    }
    float v;
    v = a0 + b1[c0]; g_H1O[(size_t)n * C1 + c0] = v > 0.f ? v : expm1f(v);
    v = a1 + b1[c1]; g_H1O[(size_t)n * C1 + c1] = v > 0.f ? v : expm1f(v);
    v = a2 + b1[c2]; g_H1O[(size_t)n * C1 + c2] = v > 0.f ? v : expm1f(v);
    if (c3 < C1) { v = a3 + b1[c3]; g_H1O[(size_t)n * C1 + c3] = v > 0.f ? v : expm1f(v); }
}

// ---------------- layer 2 softmax / aggregation + readout -------------------
__global__ void k_compact2() {
    int n = blockIdx.x * blockDim.x + threadIdx.x;
    if (n >= N_NODES) return;
    g_AS2[n] = g_H2[n * C2A + OUT2];
    g_AD2[n] = g_H2[n * C2A + OUT2 + 1];
}
__global__ void k_softmax2() {
    int n = blockIdx.x * blockDim.x + threadIdx.x;
    if (n >= N_NODES) return;
    float adst = g_AD2[n];
    int p0 = g_OFF[n], p1 = g_OFF[n + 1];
    float m = -1e30f;
    for (int p = p0; p < p1; p++) {
        float e = g_AS2[g_CSRC[p]] + adst;
        e = e > 0.f ? e : 0.2f * e;
        m = fmaxf(m, e);
    }
    float den = 0.f;
    for (int p = p0; p < p1; p++) {
        float e = g_AS2[g_CSRC[p]] + adst;
        e = e > 0.f ? e : 0.2f * e;
        den += expf(e - m);
    }
    g_M2[n] = m;
    g_RD2[n] = 1.f / (den + 1e-16f);
}
__global__ void k_zero_readout() {
    int i = blockIdx.x * blockDim.x + threadIdx.x;
    if (i < N_GRAPHS * OUT2) { g_HSUM[i] = 0.f; g_HMAX[i] = 0.f; }
}
__global__ void k_agg2(const float* __restrict__ b2, const float* __restrict__ wg,
                       const float* __restrict__ bg, const int* __restrict__ batch) {
    int n = blockIdx.x, tid = threadIdx.x;
    __shared__ int ssrc[16];
    __shared__ float sal[16];
    __shared__ float red[128];
    float adst = g_AD2[n], m = g_M2[n], rd = g_RD2[n];
    float acc = 0.f;
    int p0 = g_OFF[n], p1 = g_OFF[n + 1];
    for (int p = p0; p < p1; p += 16) {
        int cnt = min(16, p1 - p);
        __syncthreads();
        if (tid < cnt) {
            int s = g_CSRC[p + tid];
            ssrc[tid] = s;
            float ev = g_AS2[s] + adst;
            ev = ev > 0.f ? ev : 0.2f * ev;
            sal[tid] = expf(ev - m) * rd;
        }
        __syncthreads();
        for (int e = 0; e < cnt; e++)
            acc = fmaf(sal[e], g_H2[(size_t)ssrc[e] * C2A + tid], acc);
    }
    float v = fmaxf(acc + b2[tid], 0.f);
    red[tid] = v * wg[tid];
    __syncthreads();
    for (int o = 64; o > 0; o >>= 1) {
        if (tid < o) red[tid] += red[tid + o];
        __syncthreads();
    }
    float w = 1.f / (1.f + expf(-(red[0] + bg[0])));
    int g = batch[n];
    atomicAdd(&g_HSUM[g * OUT2 + tid], v * w);
    atomicMax((int*)&g_HMAX[g * OUT2 + tid], __float_as_int(v));  // v >= 0
}

// ---------------- tail ------------------------------------------------------
__global__ void k_concat() {
    int i = blockIdx.x * blockDim.x + threadIdx.x;
    if (i >= N_GRAPHS * 512) return;
    int g = i / 512, c = i - g * 512;
    float v;
    if (c < 128)      v = g_HSUM[g * 128 + c];
    else if (c < 256) v = g_HMAX[g * 128 + (c - 128)];
    else              v = g_XT[g * 256 + (c - 256)];
    g_XC[i] = v;
}
__global__ void k_out(const float* __restrict__ Wo, const float* __restrict__ bo,
                      float* __restrict__ out) {
    int g = blockIdx.x, lane = threadIdx.x;
    float s = 0.f;
    for (int k = lane; k < 256; k += 32) s += g_X2[g * 256 + k] * Wo[k];
#pragma unroll
    for (int o = 16; o > 0; o >>= 1) s += __shfl_down_sync(0xffffffffu, s, o);
    if (lane == 0) out[g] = s + bo[0];
}

// ---------------- host ------------------------------------------------------
static inline dim3 mma_grid(int M, int N) {
    return dim3((M + 63) / 64, (N + 63) / 64);
}

extern "C" void kernel_launch(void* const* d_in, const int* in_sizes, int n_in,
                              void* d_out, int out_size) {
    const float* x      = (const float*)d_in[0];
    const int*   ei     = (const int*)d_in[1];
    const int*   batch  = (const int*)d_in[2];
    const float* target = (const float*)d_in[3];
    const float* W1  = (const float*)d_in[4];
    const float* as1 = (const float*)d_in[5];
    const float* ad1 = (const float*)d_in[6];
    const float* b1  = (const float*)d_in[7];
    const float* W2  = (const float*)d_in[8];
    const float* as2 = (const float*)d_in[9];
    const float* ad2 = (const float*)d_in[10];
    const float* b2  = (const float*)d_in[11];
    const float* wg  = (const float*)d_in[12];
    const float* bg  = (const float*)d_in[13];
    const float* Wxt = (const float*)d_in[14];
    const float* bxt = (const float*)d_in[15];
    const float* Wf1 = (const float*)d_in[16];
    const float* bf1 = (const float*)d_in[17];
    const float* Wf2 = (const float*)d_in[18];
    const float* bf2 = (const float*)d_in[19];
    const float* Wo  = (const float*)d_in[20];
    const float* bo  = (const float*)d_in[21];
    float* out = (float*)d_out;

    float *H1, *H1O, *H2, *W1A, *W2A, *XT, *XC, *X1, *X2;
    cudaGetSymbolAddress((void**)&H1,  g_H1);
    cudaGetSymbolAddress((void**)&H1O, g_H1O);
    cudaGetSymbolAddress((void**)&H2,  g_H2);
    cudaGetSymbolAddress((void**)&W1A, g_W1A);
    cudaGetSymbolAddress((void**)&W2A, g_W2A);
    cudaGetSymbolAddress((void**)&XT,  g_XT);
    cudaGetSymbolAddress((void**)&XC,  g_XC);
    cudaGetSymbolAddress((void**)&X1,  g_X1);
    cudaGetSymbolAddress((void**)&X2,  g_X2);

    // CSR build
    k_initdeg<<<(N_NODES + 255) / 256, 256>>>();
    k_hist<<<(N_EDGES + 255) / 256, 256>>>(ei);
    k_scan1<<<NB_SCAN, 1024>>>();
    k_scan2<<<1, 128>>>();
    k_scan3<<<(N_NODES + 255) / 256, 256>>>();
    k_scatter<<<(E_TOT + 255) / 256, 256>>>(ei);

    // weight augmentation
    k_prep1<<<(F_IN * C1A + 255) / 256, 256>>>(W1, as1, ad1);
    k_prep2<<<(C1 * C2A + 255) / 256, 256>>>(W2, as2, ad2);

    // layer 1: H1 = x @ W1A   [100000,78]x[78,800]
    k_mma<<<mma_grid(N_NODES, C1A), 128>>>(x, W1A, nullptr, H1,
                                           N_NODES, F_IN, C1A, C1A, 0);
    k_compact1<<<(N_NODES * H1N + 255) / 256, 256>>>();
    k_softmax1<<<(N_NODES * H1N + 255) / 256, 256>>>();
    k_agg1<<<N_NODES, 256>>>(b1);

    // layer 2: H2 = H1O @ W2A   [100000,780]x[780,130]
    k_mma<<<mma_grid(N_NODES, C2A), 128>>>(H1O, W2A, nullptr, H2,
                                           N_NODES, C1, C2A, C2A, 0);
    k_compact2<<<(N_NODES + 255) / 256, 256>>>();
    k_softmax2<<<(N_NODES + 255) / 256, 256>>>();
    k_zero_readout<<<(N_GRAPHS * OUT2 + 255) / 256, 256>>>();
    k_agg2<<<N_NODES, 128>>>(b2, wg, bg, batch);

    // tail MLP
    k_mma<<<mma_grid(N_GRAPHS, 256), 128>>>(target, Wxt, bxt, XT,
                                            N_GRAPHS, 1280, 256, 256, 0);
    k_concat<<<(N_GRAPHS * 512 + 255) / 256, 256>>>();
    k_mma<<<mma_grid(N_GRAPHS, 1024), 128>>>(XC, Wf1, bf1, X1,
                                             N_GRAPHS, 512, 1024, 1024, 1);
    k_mma<<<mma_grid(N_GRAPHS, 256), 128>>>(X1, Wf2, bf2, X2,
                                            N_GRAPHS, 1024, 256, 256, 1);
    k_out<<<N_GRAPHS, 32>>>(Wo, bo, out);
}